// round 2
// baseline (speedup 1.0000x reference)
#include <cuda_runtime.h>
#include <math.h>

#define BATCH 4
#define CDIM  256
#define HEADS 8
#define CH    32
#define DH    96      // CH*3, attention head feature dim
#define SEQ   2048
#define EPSB  1e-6f

// Scratch: q,k,z,att stored as [b][h][n][f], f = ch*3 + d  (row-major, 96 floats per token)
__device__ float g_q[BATCH*HEADS*SEQ*DH];
__device__ float g_k[BATCH*HEADS*SEQ*DH];
__device__ float g_z[BATCH*HEADS*SEQ*DH];
__device__ float g_att[BATCH*HEADS*SEQ*DH];

// ---------------------------------------------------------------------------
// Kernel 1: fused VN-linears for Q,K,Z.
// y[b,e,d,n] = sum_c X[b,c,d,n]*W[c,e] + EPS*bias[e,d]/||bias[e,:]||
// CTA tile: 64 e-rows (2 heads) x 192 cols (3 d x 64 n), K=256.
// Output staged through smem -> fully coalesced writes to g_*[b][h][n][f].
// ---------------------------------------------------------------------------
__global__ __launch_bounds__(256) void vn_in_kernel(
    const float* __restrict__ Q, const float* __restrict__ K, const float* __restrict__ Z,
    const float* __restrict__ Wq, const float* __restrict__ bq,
    const float* __restrict__ Wk, const float* __restrict__ bk,
    const float* __restrict__ Wz, const float* __restrict__ bz)
{
    __shared__ float smem[6208];           // max(4128 GEMM tiles, 64*97 staging)
    float* sW = smem;                      // [16][65]
    float* sX = smem + 1040;               // [16][193]

    const int tid = threadIdx.x;
    const int which = blockIdx.z >> 2;     // 0=Q 1=K 2=Z
    const int b  = blockIdx.z & 3;
    const int hp = blockIdx.y;             // head pair
    const int n0 = blockIdx.x * 64;
    const int e0 = hp * 64;

    const float* X  = (which == 0) ? Q  : (which == 1) ? K  : Z;
    const float* W  = (which == 0) ? Wq : (which == 1) ? Wk : Wz;
    const float* bb = (which == 0) ? bq : (which == 1) ? bk : bz;
    float* out      = (which == 0) ? g_q : (which == 1) ? g_k : g_z;

    const int ty = tid >> 5;   // 0..7  (e rows)
    const int tx = tid & 31;   // 0..31 (cols)

    float acc[8][6];
#pragma unroll
    for (int i = 0; i < 8; i++)
#pragma unroll
        for (int j = 0; j < 6; j++) acc[i][j] = 0.f;

    const float* Xb = X + (size_t)b * CDIM * 3 * SEQ;

    for (int kc = 0; kc < CDIM; kc += 16) {
        // W tile: 16 x 64 (e0..e0+64)
#pragma unroll
        for (int q = 0; q < 4; q++) {
            int idx = q * 256 + tid;
            int k = idx >> 6, r = idx & 63;
            sW[k * 65 + r] = W[(kc + k) * CDIM + e0 + r];
        }
        // X tile: 16 x 192  (cols = d*64 + nn)
#pragma unroll
        for (int q = 0; q < 12; q++) {
            int idx = q * 256 + tid;
            int k = idx / 192, c = idx % 192;
            int d = c >> 6, nn = c & 63;
            sX[k * 193 + c] = Xb[((size_t)(kc + k) * 3 + d) * SEQ + n0 + nn];
        }
        __syncthreads();
#pragma unroll
        for (int k = 0; k < 16; k++) {
            float ra[8], rb[6];
#pragma unroll
            for (int i = 0; i < 8; i++) ra[i] = sW[k * 65 + ty + 8 * i];
#pragma unroll
            for (int j = 0; j < 6; j++) rb[j] = sX[k * 193 + tx + 32 * j];
#pragma unroll
            for (int i = 0; i < 8; i++)
#pragma unroll
                for (int j = 0; j < 6; j++) acc[i][j] += ra[i] * rb[j];
        }
        __syncthreads();
    }

    // Epilogue: add bias, stage per-head [64 n][96 f] (pad 97), coalesced global write.
#pragma unroll
    for (int hl = 0; hl < 2; hl++) {
#pragma unroll
        for (int i2 = 0; i2 < 4; i2++) {
            int i = hl * 4 + i2;
            int r = ty + 8 * i;               // 32*hl .. 32*hl+31
            int ch = r & 31;
            int e = e0 + r;
            float b0 = bb[e * 3 + 0], b1 = bb[e * 3 + 1], b2 = bb[e * 3 + 2];
            float inv = EPSB * rsqrtf(b0 * b0 + b1 * b1 + b2 * b2);
            float u0 = b0 * inv, u1 = b1 * inv, u2 = b2 * inv;
#pragma unroll
            for (int j = 0; j < 6; j++) {
                int c = tx + 32 * j;
                int d = c >> 6, nn = c & 63;
                float uu = (d == 0) ? u0 : (d == 1) ? u1 : u2;
                smem[nn * 97 + ch * 3 + d] = acc[i][j] + uu;
            }
        }
        __syncthreads();
        {
            int h = hp * 2 + hl;
            size_t base = ((size_t)(b * HEADS + h) * SEQ + n0) * DH;
#pragma unroll
            for (int q = 0; q < 24; q++) {
                int off = q * 256 + tid;
                out[base + off] = smem[(off / 96) * 97 + off % 96];
            }
        }
        __syncthreads();
    }
}

// ---------------------------------------------------------------------------
// Kernel 2: flash attention, D=96, Mtile=Ntile=128, online softmax (exp2 domain).
// 256 threads: thread grid 16(ty: m) x 16(tx: n/f).
// S microtile 8x8 (rows i=ty+16*ii, cols j=tx+16*jj), O microtile 8x6.
// ---------------------------------------------------------------------------
#define MT 128
#define NT 128
#define RP 97    // padded row stride for 96-wide q/k/z tiles
#define PS 132   // padded row stride for 128-wide P tile (128+4)

extern __shared__ float dsm[];

__global__ __launch_bounds__(256, 1) void attn_kernel()
{
    float* Qs = dsm;                 // [128][97]
    float* KZ = dsm + 128 * RP;      // [128][97]  (K tile, then Z tile)
    float* Ps = dsm + 2 * 128 * RP;  // [128][132]

    const int tid = threadIdx.x;
    const int tx = tid & 15;
    const int ty = tid >> 4;

    const int b = blockIdx.z, h = blockIdx.y;
    const int m0 = blockIdx.x * MT;
    const size_t qbase  = ((size_t)(b * HEADS + h) * SEQ + m0) * DH;
    const size_t kvbase = ((size_t)(b * HEADS + h) * SEQ) * DH;

    // Load Q tile
#pragma unroll
    for (int q = 0; q < 48; q++) {
        int idx = q * 256 + tid;
        Qs[(idx / 96) * RP + idx % 96] = g_q[qbase + idx];
    }

    float O[8][6];
    float mrow[8], lrow[8];
#pragma unroll
    for (int i = 0; i < 8; i++) {
        mrow[i] = -1e30f; lrow[i] = 0.f;
#pragma unroll
        for (int j = 0; j < 6; j++) O[i][j] = 0.f;
    }

    const float SCL = 0.1020620726f * 1.44269504f;   // (1/sqrt(96)) * log2(e)

    for (int nt = 0; nt < SEQ / NT; nt++) {
        __syncthreads();     // prior PV done with KZ / Ps (and Q visible on first iter)
        size_t kb = kvbase + (size_t)nt * NT * DH;
#pragma unroll
        for (int q = 0; q < 48; q++) {
            int idx = q * 256 + tid;
            KZ[(idx / 96) * RP + idx % 96] = g_k[kb + idx];
        }
        __syncthreads();

        // S = Q K^T  (128x128, reduce over 96)
        float s[8][8];
#pragma unroll
        for (int i = 0; i < 8; i++)
#pragma unroll
            for (int j = 0; j < 8; j++) s[i][j] = 0.f;

#pragma unroll 2
        for (int k = 0; k < DH; k++) {
            float ra[8], rb[8];
#pragma unroll
            for (int i = 0; i < 8; i++) ra[i] = Qs[(ty + 16 * i) * RP + k];
#pragma unroll
            for (int j = 0; j < 8; j++) rb[j] = KZ[(tx + 16 * j) * RP + k];
#pragma unroll
            for (int i = 0; i < 8; i++)
#pragma unroll
                for (int j = 0; j < 8; j++) s[i][j] += ra[i] * rb[j];
        }

        // Online softmax per row (16 threads with same ty own a row-group)
#pragma unroll
        for (int i = 0; i < 8; i++) {
            float mx = mrow[i];
#pragma unroll
            for (int j = 0; j < 8; j++) {
                s[i][j] *= SCL;
                mx = fmaxf(mx, s[i][j]);
            }
#pragma unroll
            for (int off = 1; off < 16; off <<= 1)
                mx = fmaxf(mx, __shfl_xor_sync(0xffffffffu, mx, off));
            float alpha = exp2f(mrow[i] - mx);
            mrow[i] = mx;
            float rs = 0.f;
#pragma unroll
            for (int j = 0; j < 8; j++) {
                float p = exp2f(s[i][j] - mx);
                s[i][j] = p;
                rs += p;
            }
#pragma unroll
            for (int off = 1; off < 16; off <<= 1)
                rs += __shfl_xor_sync(0xffffffffu, rs, off);
            lrow[i] = lrow[i] * alpha + rs;
#pragma unroll
            for (int j = 0; j < 6; j++) O[i][j] *= alpha;
#pragma unroll
            for (int j = 0; j < 8; j++)
                Ps[(ty + 16 * i) * PS + tx + 16 * j] = s[i][j];
        }
        __syncthreads();     // Ps written, S-phase reads of KZ done

        // Load Z tile over K tile
#pragma unroll
        for (int q = 0; q < 48; q++) {
            int idx = q * 256 + tid;
            KZ[(idx / 96) * RP + idx % 96] = g_z[kb + idx];
        }
        __syncthreads();

        // O += P Z   (128m x 96f, reduce over 128n)
#pragma unroll 2
        for (int n = 0; n < NT; n++) {
            float rp[8], rz[6];
#pragma unroll
            for (int i = 0; i < 8; i++) rp[i] = Ps[(ty + 16 * i) * PS + n];
#pragma unroll
            for (int j = 0; j < 6; j++) rz[j] = KZ[n * RP + tx + 16 * j];
#pragma unroll
            for (int i = 0; i < 8; i++)
#pragma unroll
                for (int j = 0; j < 6; j++) O[i][j] += rp[i] * rz[j];
        }
    }

    // Normalize and write
#pragma unroll
    for (int i = 0; i < 8; i++) {
        float inv = 1.f / lrow[i];
#pragma unroll
        for (int j = 0; j < 6; j++)
            g_att[qbase + (ty + 16 * i) * DH + tx + 16 * j] = O[i][j] * inv;
    }
}

// ---------------------------------------------------------------------------
// Kernel 3: output VN-linear.
// out[b,e,d,m] = sum_c att[b,c,d,m]*Wo[c,e] + u[e,d],  c = h*32+ch, att[b][h][m][ch*3+d]
// CTA: 64 e x (3 d x 64 m), K=256 in chunks of 16 (one 48-wide f window per chunk).
// ---------------------------------------------------------------------------
__global__ __launch_bounds__(256) void vn_out_kernel(
    const float* __restrict__ Wo, const float* __restrict__ bo, float* __restrict__ out)
{
    __shared__ float sA[16 * 65];   // W tile 16x64
    __shared__ float sB[64 * 49];   // att tile: 64 m x 48 f

    const int tid = threadIdx.x;
    const int tx = tid & 15;
    const int ty = tid >> 4;
    const int b = blockIdx.z;
    const int e0 = blockIdx.y * 64;
    const int m0 = blockIdx.x * 64;

    float acc[4][12];
#pragma unroll
    for (int i = 0; i < 4; i++)
#pragma unroll
        for (int j = 0; j < 12; j++) acc[i][j] = 0.f;

    for (int kc = 0; kc < CDIM; kc += 16) {
        int h = kc >> 5;
        int f0 = (kc & 31) * 3;
#pragma unroll
        for (int q = 0; q < 4; q++) {
            int idx = q * 256 + tid;
            int k = idx >> 6, r = idx & 63;
            sA[k * 65 + r] = Wo[(kc + k) * CDIM + e0 + r];
        }
#pragma unroll
        for (int q = 0; q < 12; q++) {
            int idx = q * 256 + tid;
            int mm = idx / 48, ff = idx % 48;
            sB[mm * 49 + ff] = g_att[((size_t)(b * HEADS + h) * SEQ + m0 + mm) * DH + f0 + ff];
        }
        __syncthreads();
#pragma unroll
        for (int k = 0; k < 16; k++) {
            float ra[4], rb[12];
#pragma unroll
            for (int i = 0; i < 4; i++) ra[i] = sA[k * 65 + ty + 16 * i];
#pragma unroll
            for (int j = 0; j < 12; j++) {
                int c = tx + 16 * j;
                int d = c >> 6, mm = c & 63;
                rb[j] = sB[mm * 49 + k * 3 + d];
            }
#pragma unroll
            for (int i = 0; i < 4; i++)
#pragma unroll
                for (int j = 0; j < 12; j++) acc[i][j] += ra[i] * rb[j];
        }
        __syncthreads();
    }

#pragma unroll
    for (int i = 0; i < 4; i++) {
        int e = e0 + ty + 16 * i;
        float b0 = bo[e * 3 + 0], b1 = bo[e * 3 + 1], b2 = bo[e * 3 + 2];
        float inv = EPSB * rsqrtf(b0 * b0 + b1 * b1 + b2 * b2);
        float u0 = b0 * inv, u1 = b1 * inv, u2 = b2 * inv;
#pragma unroll
        for (int j = 0; j < 12; j++) {
            int c = tx + 16 * j;
            int d = c >> 6, mm = c & 63;
            float uu = (d == 0) ? u0 : (d == 1) ? u1 : u2;
            out[(((size_t)b * CDIM + e) * 3 + d) * SEQ + m0 + mm] = acc[i][j] + uu;
        }
    }
}

// ---------------------------------------------------------------------------
extern "C" void kernel_launch(void* const* d_in, const int* in_sizes, int n_in,
                              void* d_out, int out_size)
{
    const float* Q   = (const float*)d_in[0];
    const float* K   = (const float*)d_in[1];
    const float* Z   = (const float*)d_in[2];
    const float* Wqw = (const float*)d_in[3];
    const float* Wqb = (const float*)d_in[4];
    const float* Wkw = (const float*)d_in[5];
    const float* Wkb = (const float*)d_in[6];
    const float* Wzw = (const float*)d_in[7];
    const float* Wzb = (const float*)d_in[8];
    const float* Wow = (const float*)d_in[9];
    const float* Wob = (const float*)d_in[10];
    float* out = (float*)d_out;

    const int attn_smem = (2 * 128 * RP + 128 * PS) * (int)sizeof(float);   // 166912 B
    cudaFuncSetAttribute(attn_kernel, cudaFuncAttributeMaxDynamicSharedMemorySize, attn_smem);

    vn_in_kernel<<<dim3(SEQ / 64, HEADS / 2, 3 * BATCH), 256>>>(
        Q, K, Z, Wqw, Wqb, Wkw, Wkb, Wzw, Wzb);
    attn_kernel<<<dim3(SEQ / MT, HEADS, BATCH), 256, attn_smem>>>();
    vn_out_kernel<<<dim3(SEQ / 64, CDIM / 64, BATCH), 256>>>(Wow, Wob, out);
}

// round 8
// speedup vs baseline: 2.5860x; 2.5860x over previous
#include <cuda_runtime.h>
#include <cuda_fp16.h>
#include <stdint.h>
#include <math.h>

#define BATCH 4
#define CDIM  256
#define HEADS 8
#define DH    96
#define SEQ   2048
#define EPSB  1e-6f

// fp16 scratch (packed f16x2 words): g_q,g_k,g_z: [bh][n][48 words], f = ch*3+d packed in pairs
__device__ unsigned g_q[BATCH*HEADS*SEQ*48];
__device__ unsigned g_k[BATCH*HEADS*SEQ*48];
__device__ unsigned g_z[BATCH*HEADS*SEQ*48];
__device__ float    g_att[BATCH*HEADS*SEQ*DH];

__device__ __forceinline__ uint32_t smem_u32(const void* p) {
    uint32_t a;
    asm("{ .reg .u64 t; cvta.to.shared.u64 t, %1; cvt.u32.u64 %0, t; }" : "=r"(a) : "l"(p));
    return a;
}
__device__ __forceinline__ unsigned pack_h2(float lo, float hi) {
    unsigned u;
    asm("cvt.rn.f16x2.f32 %0, %1, %2;" : "=r"(u) : "f"(hi), "f"(lo));
    return u;
}
__device__ __forceinline__ float fexp2(float x) {
    x = fminf(fmaxf(x, -24.f), 14.f);
    float fx = x + 12582912.f;                    // round-to-int trick
    int   n  = __float_as_int(fx) - 0x4B400000;
    float r  = x - (fx - 12582912.f);
    float p  = 1.33335581e-3f;
    p = fmaf(p, r, 9.61812910e-3f);
    p = fmaf(p, r, 5.55041086e-2f);
    p = fmaf(p, r, 2.40226507e-1f);
    p = fmaf(p, r, 6.93147182e-1f);
    p = fmaf(p, r, 1.0f);
    return __int_as_float(__float_as_int(p) + (n << 23));
}

#define LDSM4(r, ad) \
    asm volatile("ldmatrix.sync.aligned.m8n8.x4.shared.b16 {%0,%1,%2,%3},[%4];" \
        : "=r"((r)[0]),"=r"((r)[1]),"=r"((r)[2]),"=r"((r)[3]) : "r"(ad))
#define LDSM2(r0, r1, ad) \
    asm volatile("ldmatrix.sync.aligned.m8n8.x2.shared.b16 {%0,%1},[%2];" \
        : "=r"(r0),"=r"(r1) : "r"(ad))
#define LDSM2T(r0, r1, ad) \
    asm volatile("ldmatrix.sync.aligned.m8n8.x2.trans.shared.b16 {%0,%1},[%2];" \
        : "=r"(r0),"=r"(r1) : "r"(ad))
#define MMA16816(d, a, b0, b1) \
    asm volatile("mma.sync.aligned.m16n8k16.row.col.f32.f16.f16.f32 " \
        "{%0,%1,%2,%3},{%4,%5,%6,%7},{%8,%9},{%0,%1,%2,%3};" \
        : "+f"((d)[0]),"+f"((d)[1]),"+f"((d)[2]),"+f"((d)[3]) \
        : "r"((a)[0]),"r"((a)[1]),"r"((a)[2]),"r"((a)[3]), "r"(b0),"r"(b1))

// ---------------------------------------------------------------------------
// Kernel 1: fused VN-linears for Q,K,Z (fp32 GEMM, packed fp16 outputs)
// ---------------------------------------------------------------------------
__global__ __launch_bounds__(256) void vn_in_kernel(
    const float* __restrict__ Q, const float* __restrict__ K, const float* __restrict__ Z,
    const float* __restrict__ Wq, const float* __restrict__ bq,
    const float* __restrict__ Wk, const float* __restrict__ bk,
    const float* __restrict__ Wz, const float* __restrict__ bz)
{
    __shared__ float smem[6208];
    float* sW = smem;                      // [16][65]
    float* sX = smem + 1040;               // [16][193]

    const int tid = threadIdx.x;
    const int which = blockIdx.z >> 2;
    const int b  = blockIdx.z & 3;
    const int hp = blockIdx.y;
    const int n0 = blockIdx.x * 64;
    const int e0 = hp * 64;

    const float* X  = (which == 0) ? Q  : (which == 1) ? K  : Z;
    const float* W  = (which == 0) ? Wq : (which == 1) ? Wk : Wz;
    const float* bb = (which == 0) ? bq : (which == 1) ? bk : bz;
    unsigned* og    = (which == 0) ? g_q : (which == 1) ? g_k : g_z;

    const int ty = tid >> 5, tx = tid & 31;

    float acc[8][6];
#pragma unroll
    for (int i = 0; i < 8; i++)
#pragma unroll
        for (int j = 0; j < 6; j++) acc[i][j] = 0.f;

    const float* Xb = X + (size_t)b * CDIM * 3 * SEQ;

    for (int kc = 0; kc < CDIM; kc += 16) {
#pragma unroll
        for (int q = 0; q < 4; q++) {
            int idx = q * 256 + tid, k = idx >> 6, r = idx & 63;
            sW[k * 65 + r] = W[(kc + k) * CDIM + e0 + r];
        }
#pragma unroll
        for (int q = 0; q < 12; q++) {
            int idx = q * 256 + tid, k = idx / 192, c = idx % 192;
            sX[k * 193 + c] = Xb[((size_t)(kc + k) * 3 + (c >> 6)) * SEQ + n0 + (c & 63)];
        }
        __syncthreads();
#pragma unroll
        for (int k = 0; k < 16; k++) {
            float ra[8], rb[6];
#pragma unroll
            for (int i = 0; i < 8; i++) ra[i] = sW[k * 65 + ty + 8 * i];
#pragma unroll
            for (int j = 0; j < 6; j++) rb[j] = sX[k * 193 + tx + 32 * j];
#pragma unroll
            for (int i = 0; i < 8; i++)
#pragma unroll
                for (int j = 0; j < 6; j++) acc[i][j] += ra[i] * rb[j];
        }
        __syncthreads();
    }

#pragma unroll
    for (int hl = 0; hl < 2; hl++) {
#pragma unroll
        for (int i2 = 0; i2 < 4; i2++) {
            int i = hl * 4 + i2;
            int r = ty + 8 * i, ch = r & 31, e = e0 + r;
            float b0 = bb[e * 3 + 0], b1 = bb[e * 3 + 1], b2 = bb[e * 3 + 2];
            float inv = EPSB * rsqrtf(b0 * b0 + b1 * b1 + b2 * b2);
            float u0 = b0 * inv, u1 = b1 * inv, u2 = b2 * inv;
#pragma unroll
            for (int j = 0; j < 6; j++) {
                int c = tx + 32 * j, d = c >> 6, nn = c & 63;
                float uu = (d == 0) ? u0 : (d == 1) ? u1 : u2;
                smem[nn * 97 + ch * 3 + d] = acc[i][j] + uu;
            }
        }
        __syncthreads();
        {
            int h = hp * 2 + hl;
            unsigned* ow = og + (((size_t)b * HEADS + h) * SEQ + n0) * 48;
#pragma unroll
            for (int q = 0; q < 12; q++) {
                int w = q * 256 + tid, n = w / 48, fw = w % 48;
                ow[w] = pack_h2(smem[n * 97 + 2 * fw], smem[n * 97 + 2 * fw + 1]);
            }
        }
        __syncthreads();
    }
}

// ---------------------------------------------------------------------------
// Kernel 2: mma.sync flash attention. 8 warps x 16 q-rows, KV tiles of 128.
// S=QK^T (HMMA), poly-exp2 softmax (no max-sub), P stays in registers as
// A-fragments (free accumulator->operand conversion), O += P*Z (HMMA).
// ---------------------------------------------------------------------------
#define NSTR 52                                 // smem row stride in words (104 halves)
#define ATT_SMEM (3 * 128 * NSTR * 4)           // 79872 B

__global__ void __launch_bounds__(256, 1) attn_kernel()
{
    extern __shared__ unsigned dsm[];
    unsigned* sQ = dsm;                 // [128][52]
    unsigned* sK = sQ + 128 * NSTR;
    unsigned* sZ = sK + 128 * NSTR;

    const int tid = threadIdx.x;
    const int w   = tid >> 5;
    const int lane = tid & 31;
    const int b = blockIdx.z, h = blockIdx.y;
    const int m0 = blockIdx.x * 128;
    const size_t bh = (size_t)(b * HEADS + h);

    const unsigned* gq = g_q + (bh * SEQ + m0) * 48;
    const unsigned* gk = g_k + bh * SEQ * 48;
    const unsigned* gz = g_z + bh * SEQ * 48;

    // stage Q
    for (int i = tid; i < 6144; i += 256) {
        int n = i / 48, fw = i % 48;
        sQ[n * NSTR + fw] = gq[n * 48 + fw];
    }
    __syncthreads();

    const uint32_t sQb = smem_u32(sQ), sKb = smem_u32(sK), sZb = smem_u32(sZ);
    const int l8 = lane & 7;
    const int khalf = ((lane >> 3) & 1) * 8;    // matrix-pair column offset

    // Q fragments: 6 k-tiles, row.col A operand
    unsigned aQ[6][4];
#pragma unroll
    for (int kt = 0; kt < 6; kt++) {
        uint32_t ad = sQb + (uint32_t)((w * 16 + l8 + khalf) * (2 * NSTR) + kt * 16 + (lane >> 4) * 8) * 2u;
        LDSM4(aQ[kt], ad);
    }

    float o[12][4];
#pragma unroll
    for (int ft = 0; ft < 12; ft++)
#pragma unroll
        for (int c = 0; c < 4; c++) o[ft][c] = 0.f;
    float l0 = 0.f, l1 = 0.f;
    const float SCL2 = 0.1472441765f;           // (1/sqrt(96)) * log2(e)

    for (int nt = 0; nt < 16; nt++) {
        __syncthreads();
        for (int i = tid; i < 6144; i += 256) {
            int n = i / 48, fw = i % 48;
            sK[n * NSTR + fw] = gk[(size_t)(nt * 128 + n) * 48 + fw];
            sZ[n * NSTR + fw] = gz[(size_t)(nt * 128 + n) * 48 + fw];
        }
        __syncthreads();

        unsigned P[8][4];
#pragma unroll
        for (int jj = 0; jj < 8; jj++) {
            float s0[4] = {0.f, 0.f, 0.f, 0.f}, s1[4] = {0.f, 0.f, 0.f, 0.f};
            int n0 = jj * 16;
#pragma unroll
            for (int kt = 0; kt < 6; kt++) {
                unsigned b0, b1;
                uint32_t ad = sKb + (uint32_t)((n0 + l8) * (2 * NSTR) + kt * 16 + khalf) * 2u;
                LDSM2(b0, b1, ad);
                MMA16816(s0, aQ[kt], b0, b1);
            }
#pragma unroll
            for (int kt = 0; kt < 6; kt++) {
                unsigned b0, b1;
                uint32_t ad = sKb + (uint32_t)((n0 + 8 + l8) * (2 * NSTR) + kt * 16 + khalf) * 2u;
                LDSM2(b0, b1, ad);
                MMA16816(s1, aQ[kt], b0, b1);
            }
            float e00 = fexp2(s0[0] * SCL2), e01 = fexp2(s0[1] * SCL2);
            float e02 = fexp2(s0[2] * SCL2), e03 = fexp2(s0[3] * SCL2);
            float e10 = fexp2(s1[0] * SCL2), e11 = fexp2(s1[1] * SCL2);
            float e12 = fexp2(s1[2] * SCL2), e13 = fexp2(s1[3] * SCL2);
            l0 += (e00 + e01) + (e10 + e11);
            l1 += (e02 + e03) + (e12 + e13);
            P[jj][0] = pack_h2(e00, e01);       // row g,   k cols 2q,2q+1
            P[jj][1] = pack_h2(e02, e03);       // row g+8
            P[jj][2] = pack_h2(e10, e11);       // row g,   k cols +8
            P[jj][3] = pack_h2(e12, e13);       // row g+8
        }

#pragma unroll
        for (int kk = 0; kk < 8; kk++) {
#pragma unroll
            for (int ft = 0; ft < 12; ft++) {
                unsigned b0, b1;
                uint32_t ad = sZb + (uint32_t)((kk * 16 + l8 + khalf) * (2 * NSTR) + ft * 8) * 2u;
                LDSM2T(b0, b1, ad);
                MMA16816(o[ft], P[kk], b0, b1);
            }
        }
    }

    // row-sum reduction across the quad (lanes sharing t/4)
    l0 += __shfl_xor_sync(0xffffffffu, l0, 1);
    l0 += __shfl_xor_sync(0xffffffffu, l0, 2);
    l1 += __shfl_xor_sync(0xffffffffu, l1, 1);
    l1 += __shfl_xor_sync(0xffffffffu, l1, 2);
    float inv0 = 1.f / l0, inv1 = 1.f / l1;

    int grow = m0 + w * 16 + (lane >> 2);
    float* ga = g_att + (bh * SEQ + grow) * 96;
    float* gb = ga + 8 * 96;
#pragma unroll
    for (int ft = 0; ft < 12; ft++) {
        int col = ft * 8 + (lane & 3) * 2;
        ga[col]     = o[ft][0] * inv0;
        ga[col + 1] = o[ft][1] * inv0;
        gb[col]     = o[ft][2] * inv1;
        gb[col + 1] = o[ft][3] * inv1;
    }
}

// ---------------------------------------------------------------------------
// Kernel 3: output VN-linear (fp32, reads g_att)
// ---------------------------------------------------------------------------
__global__ __launch_bounds__(256) void vn_out_kernel(
    const float* __restrict__ Wo, const float* __restrict__ bo, float* __restrict__ out)
{
    __shared__ float sA[16 * 65];
    __shared__ float sB[64 * 49];

    const int tid = threadIdx.x;
    const int tx = tid & 15, ty = tid >> 4;
    const int b = blockIdx.z;
    const int e0 = blockIdx.y * 64;
    const int m0 = blockIdx.x * 64;

    float acc[4][12];
#pragma unroll
    for (int i = 0; i < 4; i++)
#pragma unroll
        for (int j = 0; j < 12; j++) acc[i][j] = 0.f;

    for (int kc = 0; kc < CDIM; kc += 16) {
        int h = kc >> 5, f0 = (kc & 31) * 3;
#pragma unroll
        for (int q = 0; q < 4; q++) {
            int idx = q * 256 + tid, k = idx >> 6, r = idx & 63;
            sA[k * 65 + r] = Wo[(kc + k) * CDIM + e0 + r];
        }
#pragma unroll
        for (int q = 0; q < 12; q++) {
            int idx = q * 256 + tid, mm = idx / 48, ff = idx % 48;
            sB[mm * 49 + ff] = g_att[((size_t)(b * HEADS + h) * SEQ + m0 + mm) * DH + f0 + ff];
        }
        __syncthreads();
#pragma unroll
        for (int k = 0; k < 16; k++) {
            float ra[4], rb[12];
#pragma unroll
            for (int i = 0; i < 4; i++) ra[i] = sA[k * 65 + ty + 16 * i];
#pragma unroll
            for (int j = 0; j < 12; j++) {
                int c = tx + 16 * j;
                rb[j] = sB[(c & 63) * 49 + k * 3 + (c >> 6)];
            }
#pragma unroll
            for (int i = 0; i < 4; i++)
#pragma unroll
                for (int j = 0; j < 12; j++) acc[i][j] += ra[i] * rb[j];
        }
        __syncthreads();
    }

#pragma unroll
    for (int i = 0; i < 4; i++) {
        int e = e0 + ty + 16 * i;
        float b0 = bo[e * 3 + 0], b1 = bo[e * 3 + 1], b2 = bo[e * 3 + 2];
        float inv = EPSB * rsqrtf(b0 * b0 + b1 * b1 + b2 * b2);
        float u0 = b0 * inv, u1 = b1 * inv, u2 = b2 * inv;
#pragma unroll
        for (int j = 0; j < 12; j++) {
            int c = tx + 16 * j, d = c >> 6, mm = c & 63;
            float uu = (d == 0) ? u0 : (d == 1) ? u1 : u2;
            out[(((size_t)b * CDIM + e) * 3 + d) * SEQ + m0 + mm] = acc[i][j] + uu;
        }
    }
}

// ---------------------------------------------------------------------------
extern "C" void kernel_launch(void* const* d_in, const int* in_sizes, int n_in,
                              void* d_out, int out_size)
{
    const float* Q   = (const float*)d_in[0];
    const float* K   = (const float*)d_in[1];
    const float* Z   = (const float*)d_in[2];
    const float* Wqw = (const float*)d_in[3];
    const float* Wqb = (const float*)d_in[4];
    const float* Wkw = (const float*)d_in[5];
    const float* Wkb = (const float*)d_in[6];
    const float* Wzw = (const float*)d_in[7];
    const float* Wzb = (const float*)d_in[8];
    const float* Wow = (const float*)d_in[9];
    const float* Wob = (const float*)d_in[10];
    float* out = (float*)d_out;

    cudaFuncSetAttribute(attn_kernel, cudaFuncAttributeMaxDynamicSharedMemorySize, ATT_SMEM);

    vn_in_kernel<<<dim3(SEQ / 64, HEADS / 2, 3 * BATCH), 256>>>(
        Q, K, Z, Wqw, Wqb, Wkw, Wkb, Wzw, Wzb);
    attn_kernel<<<dim3(SEQ / 128, HEADS, BATCH), 256, ATT_SMEM>>>();
    vn_out_kernel<<<dim3(SEQ / 64, CDIM / 64, BATCH), 256>>>(Wow, Wob, out);
}

// round 10
// speedup vs baseline: 3.9067x; 1.5107x over previous
#include <cuda_runtime.h>
#include <cuda_fp16.h>
#include <stdint.h>
#include <math.h>

#define BATCH 4
#define CDIM  256
#define HEADS 8
#define DH    96
#define SEQ   2048
#define EPSB  1e-6f

// fp16 scratch: g_q,g_k,g_z packed f16x2 [bh][n][48 words]; g_att2 half [b][d][c][m]
__device__ unsigned g_q[BATCH*HEADS*SEQ*48];
__device__ unsigned g_k[BATCH*HEADS*SEQ*48];
__device__ unsigned g_z[BATCH*HEADS*SEQ*48];
__device__ __half   g_att2[(size_t)BATCH*3*CDIM*SEQ];

__device__ __forceinline__ uint32_t smem_u32(const void* p) {
    uint32_t a;
    asm("{ .reg .u64 t; cvta.to.shared.u64 t, %1; cvt.u32.u64 %0, t; }" : "=r"(a) : "l"(p));
    return a;
}
__device__ __forceinline__ unsigned pack_h2(float lo, float hi) {
    unsigned u;
    asm("cvt.rn.f16x2.f32 %0, %1, %2;" : "=r"(u) : "f"(hi), "f"(lo));
    return u;
}
__device__ __forceinline__ float fexp2(float x) {
    x = fminf(fmaxf(x, -24.f), 14.f);
    float fx = x + 12582912.f;
    int   n  = __float_as_int(fx) - 0x4B400000;
    float r  = x - (fx - 12582912.f);
    float p  = 1.33335581e-3f;
    p = fmaf(p, r, 9.61812910e-3f);
    p = fmaf(p, r, 5.55041086e-2f);
    p = fmaf(p, r, 2.40226507e-1f);
    p = fmaf(p, r, 6.93147182e-1f);
    p = fmaf(p, r, 1.0f);
    return __int_as_float(__float_as_int(p) + (n << 23));
}

#define LDSM4(r, ad) \
    asm volatile("ldmatrix.sync.aligned.m8n8.x4.shared.b16 {%0,%1,%2,%3},[%4];" \
        : "=r"((r)[0]),"=r"((r)[1]),"=r"((r)[2]),"=r"((r)[3]) : "r"(ad))
#define LDSM4T(r, ad) \
    asm volatile("ldmatrix.sync.aligned.m8n8.x4.trans.shared.b16 {%0,%1,%2,%3},[%4];" \
        : "=r"((r)[0]),"=r"((r)[1]),"=r"((r)[2]),"=r"((r)[3]) : "r"(ad))
#define LDSM2(r0, r1, ad) \
    asm volatile("ldmatrix.sync.aligned.m8n8.x2.shared.b16 {%0,%1},[%2];" \
        : "=r"(r0),"=r"(r1) : "r"(ad))
#define LDSM2T(r0, r1, ad) \
    asm volatile("ldmatrix.sync.aligned.m8n8.x2.trans.shared.b16 {%0,%1},[%2];" \
        : "=r"(r0),"=r"(r1) : "r"(ad))
#define MMA16816(d, a, b0, b1) \
    asm volatile("mma.sync.aligned.m16n8k16.row.col.f32.f16.f16.f32 " \
        "{%0,%1,%2,%3},{%4,%5,%6,%7},{%8,%9},{%0,%1,%2,%3};" \
        : "+f"((d)[0]),"+f"((d)[1]),"+f"((d)[2]),"+f"((d)[3]) \
        : "r"((a)[0]),"r"((a)[1]),"r"((a)[2]),"r"((a)[3]), "r"(b0),"r"(b1))

// GEMM smem strides (halves); both ≡ 4 words mod 32 -> conflict-free ldmatrix
#define VNE 72     // sW row stride ([c][e] tile, e-extent 64)
#define VNX 392    // sX row stride ([c][col] tile, col-extent 384)
#define VNO 200    // vn_in staging row stride ([n][192 halves])
#define VN_IN_SMEM 51200

// ---------------------------------------------------------------------------
// Kernel 1: VN-linears for Q,K,Z on HMMA.
// Y[e, d*128+n] = sum_c W[c][e] * X[c][d][n0+n], fp16 operands, fp32 accum.
// CTA: 64 e x 384 cols, K=256 in 16-chunks. 8 warps: 4(e) x 2(cols 192).
// ---------------------------------------------------------------------------
__global__ __launch_bounds__(256, 1) void vn_in_kernel(
    const float* __restrict__ Q, const float* __restrict__ K, const float* __restrict__ Z,
    const float* __restrict__ Wq, const float* __restrict__ bq,
    const float* __restrict__ Wk, const float* __restrict__ bk,
    const float* __restrict__ Wz, const float* __restrict__ bz)
{
    extern __shared__ __half dsh[];
    __half* sW = dsh;                 // [16][VNE]
    __half* sX = dsh + 16 * VNE;      // [16][VNX]

    const int tid = threadIdx.x;
    const int w = tid >> 5, lane = tid & 31;
    const int l8 = lane & 7, g = lane >> 2, t = lane & 3;
    const int which = blockIdx.z >> 2, b = blockIdx.z & 3;
    const int ey = blockIdx.y, e0 = ey * 64;
    const int n0 = blockIdx.x * 128;

    const float* X  = (which == 0) ? Q  : (which == 1) ? K  : Z;
    const float* W  = (which == 0) ? Wq : (which == 1) ? Wk : Wz;
    const float* bb = (which == 0) ? bq : (which == 1) ? bk : bz;
    unsigned* og    = (which == 0) ? g_q : (which == 1) ? g_k : g_z;

    const float* Xb = X + (size_t)b * CDIM * 3 * SEQ;
    const int we_ = (w & 3) * 16;     // warp e offset
    const int wc_ = (w >> 2) * 192;   // warp col offset

    float o[24][4];
#pragma unroll
    for (int p = 0; p < 24; p++)
#pragma unroll
        for (int c = 0; c < 4; c++) o[p][c] = 0.f;

    const uint32_t sWb = smem_u32(sW), sXb = smem_u32(sX);
    const int arow = ((lane >> 4) & 1) * 8 + l8, acol = ((lane >> 3) & 1) * 8;
    const uint32_t aAd = sWb + (uint32_t)(arow * VNE + we_ + acol) * 2u;
    const int brow = ((lane >> 3) & 1) * 8 + l8, bcol = ((lane >> 4) & 1) * 8;
    const uint32_t bAd0 = sXb + (uint32_t)(brow * VNX + wc_ + bcol) * 2u;

    for (int kc = 0; kc < CDIM; kc += 16) {
#pragma unroll
        for (int q = 0; q < 4; q++) {
            int i = q * 256 + tid, k = i >> 6, e = i & 63;
            sW[k * VNE + e] = __float2half(W[(kc + k) * CDIM + e0 + e]);
        }
#pragma unroll
        for (int q = 0; q < 24; q++) {
            int i = q * 256 + tid, k = i / 384, col = i % 384;
            int d = col >> 7, n = col & 127;
            sX[k * VNX + col] = __float2half(Xb[((size_t)(kc + k) * 3 + d) * SEQ + n0 + n]);
        }
        __syncthreads();

        unsigned aW[4];
        LDSM4T(aW, aAd);
#pragma unroll
        for (int p = 0; p < 12; p++) {
            unsigned r[4];
            LDSM4T(r, bAd0 + (uint32_t)(p * 16) * 2u);
            MMA16816(o[2 * p],     aW, r[0], r[1]);
            MMA16816(o[2 * p + 1], aW, r[2], r[3]);
        }
        __syncthreads();
    }

    // bias vectors for this thread's two e-rows
    const int eg1 = we_ + g, eg2 = eg1 + 8;
    float u1[3], u2[3];
    {
        int e1 = e0 + eg1, e2 = e0 + eg2;
        float a0 = bb[e1 * 3], a1 = bb[e1 * 3 + 1], a2 = bb[e1 * 3 + 2];
        float inv = EPSB * rsqrtf(a0 * a0 + a1 * a1 + a2 * a2);
        u1[0] = a0 * inv; u1[1] = a1 * inv; u1[2] = a2 * inv;
        float c0 = bb[e2 * 3], c1 = bb[e2 * 3 + 1], c2 = bb[e2 * 3 + 2];
        float inw = EPSB * rsqrtf(c0 * c0 + c1 * c1 + c2 * c2);
        u2[0] = c0 * inw; u2[1] = c1 * inw; u2[2] = c2 * inw;
    }

    // stage packed-f16 [n][2 heads x 96 f] then write words coalesced
    __half* sOut = dsh;
    const int h1 = eg1 >> 5, ch1 = eg1 & 31, h2 = eg2 >> 5, ch2 = eg2 & 31;
#pragma unroll
    for (int p = 0; p < 24; p++) {
        int col = wc_ + p * 8 + t * 2;
        int d = col >> 7, n = col & 127;
        sOut[n * VNO + h1 * 96 + ch1 * 3 + d]       = __float2half(o[p][0] + u1[d]);
        sOut[(n + 1) * VNO + h1 * 96 + ch1 * 3 + d] = __float2half(o[p][1] + u1[d]);
        sOut[n * VNO + h2 * 96 + ch2 * 3 + d]       = __float2half(o[p][2] + u2[d]);
        sOut[(n + 1) * VNO + h2 * 96 + ch2 * 3 + d] = __float2half(o[p][3] + u2[d]);
    }
    __syncthreads();
    const unsigned* sOutW = (const unsigned*)dsh;
    for (int i = tid; i < 12288; i += 256) {
        int n = i / 96, wu = i % 96;
        int hl = wu / 48, fw = wu - hl * 48;
        int bh = b * HEADS + ey * 2 + hl;
        og[((size_t)bh * SEQ + n0 + n) * 48 + fw] = sOutW[n * (VNO / 2) + wu];
    }
}

// ---------------------------------------------------------------------------
// Kernel 2: mma.sync flash attention (validated R8). Output now fp16 to
// g_att2 in [b][d][c][m] layout for the vn_out HMMA B-operand.
// ---------------------------------------------------------------------------
#define NSTR 52
#define ATT_SMEM (3 * 128 * NSTR * 4)

__global__ void __launch_bounds__(256, 1) attn_kernel()
{
    extern __shared__ unsigned dsm[];
    unsigned* sQ = dsm;
    unsigned* sK = sQ + 128 * NSTR;
    unsigned* sZ = sK + 128 * NSTR;

    const int tid = threadIdx.x;
    const int w   = tid >> 5;
    const int lane = tid & 31;
    const int b = blockIdx.z, h = blockIdx.y;
    const int m0 = blockIdx.x * 128;
    const size_t bh = (size_t)(b * HEADS + h);

    const unsigned* gq = g_q + (bh * SEQ + m0) * 48;
    const unsigned* gk = g_k + bh * SEQ * 48;
    const unsigned* gz = g_z + bh * SEQ * 48;

    for (int i = tid; i < 6144; i += 256) {
        int n = i / 48, fw = i % 48;
        sQ[n * NSTR + fw] = gq[n * 48 + fw];
    }
    __syncthreads();

    const uint32_t sQb = smem_u32(sQ), sKb = smem_u32(sK), sZb = smem_u32(sZ);
    const int l8 = lane & 7;
    const int khalf = ((lane >> 3) & 1) * 8;

    unsigned aQ[6][4];
#pragma unroll
    for (int kt = 0; kt < 6; kt++) {
        uint32_t ad = sQb + (uint32_t)((w * 16 + l8 + khalf) * (2 * NSTR) + kt * 16 + (lane >> 4) * 8) * 2u;
        LDSM4(aQ[kt], ad);
    }

    float o[12][4];
#pragma unroll
    for (int ft = 0; ft < 12; ft++)
#pragma unroll
        for (int c = 0; c < 4; c++) o[ft][c] = 0.f;
    float l0 = 0.f, l1 = 0.f;
    const float SCL2 = 0.1472441765f;

    for (int nt = 0; nt < 16; nt++) {
        __syncthreads();
        for (int i = tid; i < 6144; i += 256) {
            int n = i / 48, fw = i % 48;
            sK[n * NSTR + fw] = gk[(size_t)(nt * 128 + n) * 48 + fw];
            sZ[n * NSTR + fw] = gz[(size_t)(nt * 128 + n) * 48 + fw];
        }
        __syncthreads();

        unsigned P[8][4];
#pragma unroll
        for (int jj = 0; jj < 8; jj++) {
            float s0[4] = {0.f, 0.f, 0.f, 0.f}, s1[4] = {0.f, 0.f, 0.f, 0.f};
            int n0 = jj * 16;
#pragma unroll
            for (int kt = 0; kt < 6; kt++) {
                unsigned b0, b1;
                uint32_t ad = sKb + (uint32_t)((n0 + l8) * (2 * NSTR) + kt * 16 + khalf) * 2u;
                LDSM2(b0, b1, ad);
                MMA16816(s0, aQ[kt], b0, b1);
            }
#pragma unroll
            for (int kt = 0; kt < 6; kt++) {
                unsigned b0, b1;
                uint32_t ad = sKb + (uint32_t)((n0 + 8 + l8) * (2 * NSTR) + kt * 16 + khalf) * 2u;
                LDSM2(b0, b1, ad);
                MMA16816(s1, aQ[kt], b0, b1);
            }
            float e00 = fexp2(s0[0] * SCL2), e01 = fexp2(s0[1] * SCL2);
            float e02 = fexp2(s0[2] * SCL2), e03 = fexp2(s0[3] * SCL2);
            float e10 = fexp2(s1[0] * SCL2), e11 = fexp2(s1[1] * SCL2);
            float e12 = fexp2(s1[2] * SCL2), e13 = fexp2(s1[3] * SCL2);
            l0 += (e00 + e01) + (e10 + e11);
            l1 += (e02 + e03) + (e12 + e13);
            P[jj][0] = pack_h2(e00, e01);
            P[jj][1] = pack_h2(e02, e03);
            P[jj][2] = pack_h2(e10, e11);
            P[jj][3] = pack_h2(e12, e13);
        }

#pragma unroll
        for (int kk = 0; kk < 8; kk++) {
#pragma unroll
            for (int ft = 0; ft < 12; ft++) {
                unsigned b0, b1;
                uint32_t ad = sZb + (uint32_t)((kk * 16 + l8 + khalf) * (2 * NSTR) + ft * 8) * 2u;
                LDSM2T(b0, b1, ad);
                MMA16816(o[ft], P[kk], b0, b1);
            }
        }
    }

    l0 += __shfl_xor_sync(0xffffffffu, l0, 1);
    l0 += __shfl_xor_sync(0xffffffffu, l0, 2);
    l1 += __shfl_xor_sync(0xffffffffu, l1, 1);
    l1 += __shfl_xor_sync(0xffffffffu, l1, 2);
    float inv0 = 1.f / l0, inv1 = 1.f / l1;

    int grow = m0 + w * 16 + (lane >> 2);
#pragma unroll
    for (int ft = 0; ft < 12; ft++) {
        int f0 = ft * 8 + (lane & 3) * 2, f1 = f0 + 1;
        int d0 = f0 % 3, c0 = f0 / 3, d1 = f1 % 3, c1 = f1 / 3;
        size_t a0 = ((size_t)(b * 3 + d0) * CDIM + h * 32 + c0) * SEQ + grow;
        size_t a1 = ((size_t)(b * 3 + d1) * CDIM + h * 32 + c1) * SEQ + grow;
        g_att2[a0]     = __float2half(o[ft][0] * inv0);
        g_att2[a1]     = __float2half(o[ft][1] * inv0);
        g_att2[a0 + 8] = __float2half(o[ft][2] * inv1);
        g_att2[a1 + 8] = __float2half(o[ft][3] * inv1);
    }
}

// ---------------------------------------------------------------------------
// Kernel 3: output VN-linear on HMMA.
// out[b,e,d,m] = sum_c att2[b,d,c,m] * Wo[c,e] + u[e,d], fp32 output.
// ---------------------------------------------------------------------------
__global__ __launch_bounds__(256, 1) void vn_out_kernel(
    const float* __restrict__ Wo, const float* __restrict__ bo, float* __restrict__ out)
{
    __shared__ __half sm2[16 * VNE + 16 * VNX];
    __half* sW = sm2;
    __half* sX = sm2 + 16 * VNE;

    const int tid = threadIdx.x;
    const int w = tid >> 5, lane = tid & 31;
    const int l8 = lane & 7, g = lane >> 2, t = lane & 3;
    const int b = blockIdx.z;
    const int ey = blockIdx.y, e0 = ey * 64;
    const int m0 = blockIdx.x * 128;

    const int we_ = (w & 3) * 16, wc_ = (w >> 2) * 192;
    const unsigned* att2w = (const unsigned*)g_att2;

    float o[24][4];
#pragma unroll
    for (int p = 0; p < 24; p++)
#pragma unroll
        for (int c = 0; c < 4; c++) o[p][c] = 0.f;

    const uint32_t sWb = smem_u32(sW), sXb = smem_u32(sX);
    const int arow = ((lane >> 4) & 1) * 8 + l8, acol = ((lane >> 3) & 1) * 8;
    const uint32_t aAd = sWb + (uint32_t)(arow * VNE + we_ + acol) * 2u;
    const int brow = ((lane >> 3) & 1) * 8 + l8, bcol = ((lane >> 4) & 1) * 8;
    const uint32_t bAd0 = sXb + (uint32_t)(brow * VNX + wc_ + bcol) * 2u;
    unsigned* sXw = (unsigned*)sX;

    for (int kc = 0; kc < CDIM; kc += 16) {
#pragma unroll
        for (int q = 0; q < 4; q++) {
            int i = q * 256 + tid, k = i >> 6, e = i & 63;
            sW[k * VNE + e] = __float2half(Wo[(kc + k) * CDIM + e0 + e]);
        }
#pragma unroll
        for (int q = 0; q < 12; q++) {
            int i = q * 256 + tid, k = i / 192, cw = i % 192;
            int d = cw / 64, mw = cw - d * 64;
            sXw[k * (VNX / 2) + d * 64 + mw] =
                att2w[(((size_t)(b * 3 + d) * CDIM) + kc + k) * (SEQ / 2) + (m0 >> 1) + mw];
        }
        __syncthreads();

        unsigned aW[4];
        LDSM4T(aW, aAd);
#pragma unroll
        for (int p = 0; p < 12; p++) {
            unsigned r[4];
            LDSM4T(r, bAd0 + (uint32_t)(p * 16) * 2u);
            MMA16816(o[2 * p],     aW, r[0], r[1]);
            MMA16816(o[2 * p + 1], aW, r[2], r[3]);
        }
        __syncthreads();
    }

    const int eg1 = we_ + g, eg2 = eg1 + 8;
    const int e1 = e0 + eg1, e2 = e0 + eg2;
    float u1[3], u2[3];
    {
        float a0 = bo[e1 * 3], a1 = bo[e1 * 3 + 1], a2 = bo[e1 * 3 + 2];
        float inv = EPSB * rsqrtf(a0 * a0 + a1 * a1 + a2 * a2);
        u1[0] = a0 * inv; u1[1] = a1 * inv; u1[2] = a2 * inv;
        float c0 = bo[e2 * 3], c1 = bo[e2 * 3 + 1], c2 = bo[e2 * 3 + 2];
        float inw = EPSB * rsqrtf(c0 * c0 + c1 * c1 + c2 * c2);
        u2[0] = c0 * inw; u2[1] = c1 * inw; u2[2] = c2 * inw;
    }

#pragma unroll
    for (int p = 0; p < 24; p++) {
        int col = wc_ + p * 8 + t * 2;
        int d = col >> 7, m = col & 127;
        size_t a1 = (((size_t)b * CDIM + e1) * 3 + d) * SEQ + m0 + m;
        size_t a2 = (((size_t)b * CDIM + e2) * 3 + d) * SEQ + m0 + m;
        out[a1]     = o[p][0] + u1[d];
        out[a1 + 1] = o[p][1] + u1[d];
        out[a2]     = o[p][2] + u2[d];
        out[a2 + 1] = o[p][3] + u2[d];
    }
}

// ---------------------------------------------------------------------------
extern "C" void kernel_launch(void* const* d_in, const int* in_sizes, int n_in,
                              void* d_out, int out_size)
{
    const float* Q   = (const float*)d_in[0];
    const float* K   = (const float*)d_in[1];
    const float* Z   = (const float*)d_in[2];
    const float* Wqw = (const float*)d_in[3];
    const float* Wqb = (const float*)d_in[4];
    const float* Wkw = (const float*)d_in[5];
    const float* Wkb = (const float*)d_in[6];
    const float* Wzw = (const float*)d_in[7];
    const float* Wzb = (const float*)d_in[8];
    const float* Wow = (const float*)d_in[9];
    const float* Wob = (const float*)d_in[10];
    float* out = (float*)d_out;

    cudaFuncSetAttribute(vn_in_kernel, cudaFuncAttributeMaxDynamicSharedMemorySize, VN_IN_SMEM);
    cudaFuncSetAttribute(attn_kernel, cudaFuncAttributeMaxDynamicSharedMemorySize, ATT_SMEM);

    vn_in_kernel<<<dim3(SEQ / 128, 4, 12), 256, VN_IN_SMEM>>>(
        Q, K, Z, Wqw, Wqb, Wkw, Wkb, Wzw, Wzb);
    attn_kernel<<<dim3(SEQ / 128, HEADS, BATCH), 256, ATT_SMEM>>>();
    vn_out_kernel<<<dim3(SEQ / 128, 4, BATCH), 256>>>(Wow, Wob, out);
}

// round 12
// speedup vs baseline: 5.2959x; 1.3556x over previous
#include <cuda_runtime.h>
#include <cuda_fp16.h>
#include <stdint.h>
#include <math.h>

#define BATCH 4
#define CDIM  256
#define HEADS 8
#define DH    96
#define SEQ   2048
#define EPSB  1e-6f

// fp16 scratch: g_q,g_k,g_z packed f16x2 [bh][n][48 words]; g_att2 half [b][d][c][m]
__device__ unsigned g_q[BATCH*HEADS*SEQ*48];
__device__ unsigned g_k[BATCH*HEADS*SEQ*48];
__device__ unsigned g_z[BATCH*HEADS*SEQ*48];
__device__ __half   g_att2[(size_t)BATCH*3*CDIM*SEQ];

__device__ __forceinline__ uint32_t smem_u32(const void* p) {
    uint32_t a;
    asm("{ .reg .u64 t; cvta.to.shared.u64 t, %1; cvt.u32.u64 %0, t; }" : "=r"(a) : "l"(p));
    return a;
}
__device__ __forceinline__ unsigned pack_h2(float lo, float hi) {
    unsigned u;
    asm("cvt.rn.f16x2.f32 %0, %1, %2;" : "=r"(u) : "f"(hi), "f"(lo));
    return u;
}
__device__ __forceinline__ float fexp2(float x) {
    x = fminf(fmaxf(x, -24.f), 14.f);
    float fx = x + 12582912.f;
    int   n  = __float_as_int(fx) - 0x4B400000;
    float r  = x - (fx - 12582912.f);
    float p  = 1.33335581e-3f;
    p = fmaf(p, r, 9.61812910e-3f);
    p = fmaf(p, r, 5.55041086e-2f);
    p = fmaf(p, r, 2.40226507e-1f);
    p = fmaf(p, r, 6.93147182e-1f);
    p = fmaf(p, r, 1.0f);
    return __int_as_float(__float_as_int(p) + (n << 23));
}
__device__ __forceinline__ void cp_async16(uint32_t dst, const void* src) {
    asm volatile("cp.async.cg.shared.global [%0], [%1], 16;"
                 :: "r"(dst), "l"(__cvta_generic_to_global(src)) : "memory");
}
#define CP_COMMIT() asm volatile("cp.async.commit_group;" ::: "memory")
#define CP_WAIT0()  asm volatile("cp.async.wait_group 0;" ::: "memory")

#define LDSM4(r, ad) \
    asm volatile("ldmatrix.sync.aligned.m8n8.x4.shared.b16 {%0,%1,%2,%3},[%4];" \
        : "=r"((r)[0]),"=r"((r)[1]),"=r"((r)[2]),"=r"((r)[3]) : "r"(ad))
#define LDSM4T(r, ad) \
    asm volatile("ldmatrix.sync.aligned.m8n8.x4.trans.shared.b16 {%0,%1,%2,%3},[%4];" \
        : "=r"((r)[0]),"=r"((r)[1]),"=r"((r)[2]),"=r"((r)[3]) : "r"(ad))
#define MMA16816(d, a, b0, b1) \
    asm volatile("mma.sync.aligned.m16n8k16.row.col.f32.f16.f16.f32 " \
        "{%0,%1,%2,%3},{%4,%5,%6,%7},{%8,%9},{%0,%1,%2,%3};" \
        : "+f"((d)[0]),"+f"((d)[1]),"+f"((d)[2]),"+f"((d)[3]) \
        : "r"((a)[0]),"r"((a)[1]),"r"((a)[2]),"r"((a)[3]), "r"(b0),"r"(b1))

// GEMM smem strides (halves); ≡ 4 words mod 32 -> conflict-free ldmatrix
#define VNE 72
#define VNX 392
#define VNO 200
#define VN_IN_SMEM 51200

// ---------------------------------------------------------------------------
// Kernel 1: VN-linears for Q,K,Z on HMMA. 512 threads (16 warps: 4e x 4col),
// register-prefetch of next K-chunk to hide LDG under MMAs.
// ---------------------------------------------------------------------------
__global__ __launch_bounds__(512, 1) void vn_in_kernel(
    const float* __restrict__ Q, const float* __restrict__ K, const float* __restrict__ Z,
    const float* __restrict__ Wq, const float* __restrict__ bq,
    const float* __restrict__ Wk, const float* __restrict__ bk,
    const float* __restrict__ Wz, const float* __restrict__ bz)
{
    extern __shared__ __half dsh[];
    __half* sW = dsh;                 // [16][VNE]
    __half* sX = dsh + 16 * VNE;      // [16][VNX]

    const int tid = threadIdx.x;
    const int w = tid >> 5, lane = tid & 31;
    const int l8 = lane & 7, g = lane >> 2, t = lane & 3;
    const int which = blockIdx.z >> 2, b = blockIdx.z & 3;
    const int ey = blockIdx.y, e0 = ey * 64;
    const int n0 = blockIdx.x * 128;

    const float* X  = (which == 0) ? Q  : (which == 1) ? K  : Z;
    const float* W  = (which == 0) ? Wq : (which == 1) ? Wk : Wz;
    const float* bb = (which == 0) ? bq : (which == 1) ? bk : bz;
    unsigned* og    = (which == 0) ? g_q : (which == 1) ? g_k : g_z;

    const float* Xb = X + (size_t)b * CDIM * 3 * SEQ;
    const int we_ = (w & 3) * 16;
    const int wc_ = (w >> 2) * 96;

    // per-thread load index precompute
    int wsi[2], wgi[2];
#pragma unroll
    for (int q = 0; q < 2; q++) {
        int i = q * 512 + tid, k = i >> 6, e = i & 63;
        wsi[q] = k * VNE + e;
        wgi[q] = k * CDIM + e0 + e;
    }
    int xsi[12], xgi[12];
#pragma unroll
    for (int q = 0; q < 12; q++) {
        int i = q * 512 + tid, k = i / 384, col = i % 384;
        int d = col >> 7, n = col & 127;
        xsi[q] = k * VNX + col;
        xgi[q] = (k * 3 + d) * SEQ + n0 + n;
    }

    float rW[2], rX[12];
#pragma unroll
    for (int q = 0; q < 2; q++) rW[q] = W[wgi[q]];
#pragma unroll
    for (int q = 0; q < 12; q++) rX[q] = Xb[xgi[q]];

    float o[12][4];
#pragma unroll
    for (int p = 0; p < 12; p++)
#pragma unroll
        for (int c = 0; c < 4; c++) o[p][c] = 0.f;

    const uint32_t sWb = smem_u32(sW), sXb = smem_u32(sX);
    const int arow = ((lane >> 4) & 1) * 8 + l8, acol = ((lane >> 3) & 1) * 8;
    const uint32_t aAd = sWb + (uint32_t)(arow * VNE + we_ + acol) * 2u;
    const int brow = ((lane >> 3) & 1) * 8 + l8, bcol = ((lane >> 4) & 1) * 8;
    const uint32_t bAd0 = sXb + (uint32_t)(brow * VNX + wc_ + bcol) * 2u;

    for (int kc = 0; kc < CDIM; kc += 16) {
#pragma unroll
        for (int q = 0; q < 2; q++) sW[wsi[q]] = __float2half(rW[q]);
#pragma unroll
        for (int q = 0; q < 12; q++) sX[xsi[q]] = __float2half(rX[q]);
        __syncthreads();
        if (kc + 16 < CDIM) {
#pragma unroll
            for (int q = 0; q < 2; q++) rW[q] = W[(kc + 16) * CDIM + wgi[q]];
#pragma unroll
            for (int q = 0; q < 12; q++) rX[q] = Xb[(size_t)(kc + 16) * 3 * SEQ + xgi[q]];
        }
        unsigned aW[4];
        LDSM4T(aW, aAd);
#pragma unroll
        for (int p = 0; p < 6; p++) {
            unsigned r[4];
            LDSM4T(r, bAd0 + (uint32_t)(p * 32));
            MMA16816(o[2 * p],     aW, r[0], r[1]);
            MMA16816(o[2 * p + 1], aW, r[2], r[3]);
        }
        __syncthreads();
    }

    const int eg1 = we_ + g, eg2 = eg1 + 8;
    float u1[3], u2[3];
    {
        int e1 = e0 + eg1, e2 = e0 + eg2;
        float a0 = bb[e1 * 3], a1 = bb[e1 * 3 + 1], a2 = bb[e1 * 3 + 2];
        float inv = EPSB * rsqrtf(a0 * a0 + a1 * a1 + a2 * a2);
        u1[0] = a0 * inv; u1[1] = a1 * inv; u1[2] = a2 * inv;
        float c0 = bb[e2 * 3], c1 = bb[e2 * 3 + 1], c2 = bb[e2 * 3 + 2];
        float inw = EPSB * rsqrtf(c0 * c0 + c1 * c1 + c2 * c2);
        u2[0] = c0 * inw; u2[1] = c1 * inw; u2[2] = c2 * inw;
    }

    __half* sOut = dsh;
    const int h1 = eg1 >> 5, ch1 = eg1 & 31, h2 = eg2 >> 5, ch2 = eg2 & 31;
#pragma unroll
    for (int p = 0; p < 12; p++) {
        int col = wc_ + p * 8 + t * 2;
        int d = col >> 7, n = col & 127;
        sOut[n * VNO + h1 * 96 + ch1 * 3 + d]       = __float2half(o[p][0] + u1[d]);
        sOut[(n + 1) * VNO + h1 * 96 + ch1 * 3 + d] = __float2half(o[p][1] + u1[d]);
        sOut[n * VNO + h2 * 96 + ch2 * 3 + d]       = __float2half(o[p][2] + u2[d]);
        sOut[(n + 1) * VNO + h2 * 96 + ch2 * 3 + d] = __float2half(o[p][3] + u2[d]);
    }
    __syncthreads();
    const unsigned* sOutW = (const unsigned*)dsh;
    for (int i = tid; i < 12288; i += 512) {
        int n = i / 96, wu = i % 96;
        int hl = wu / 48, fw = wu - hl * 48;
        int bh = b * HEADS + ey * 2 + hl;
        og[((size_t)bh * SEQ + n0 + n) * 48 + fw] = sOutW[n * (VNO / 2) + wu];
    }
}

// ---------------------------------------------------------------------------
// Kernel 2: mma.sync flash attention, cp.async double-buffered K/Z tiles,
// LDSM4/LDSM4T. (R11 bug fixed: full 12 chunks per 48-word row.)
// ---------------------------------------------------------------------------
#define NSTR 52
#define ATT_SMEM (5 * 128 * NSTR * 4)   // Q + 2 x (K+Z) = 133120 B

__global__ void __launch_bounds__(256, 1) attn_kernel()
{
    extern __shared__ unsigned dsm[];
    const int tid = threadIdx.x;
    const int w   = tid >> 5;
    const int lane = tid & 31;
    const int b = blockIdx.z, h = blockIdx.y;
    const int m0 = blockIdx.x * 128;
    const size_t bh = (size_t)(b * HEADS + h);

    const unsigned* gq = g_q + (bh * SEQ + m0) * 48;
    const unsigned* gk = g_k + bh * SEQ * 48;
    const unsigned* gz = g_z + bh * SEQ * 48;

    const uint32_t sQb = smem_u32(dsm);
    const uint32_t kzBase = sQb + 128 * NSTR * 4;
    const uint32_t TILE_B = 128 * NSTR * 4;

    // issue tile 0 (buf 0): 128 rows x 12 chunks x (K,Z)
    for (int i = tid; i < 1536; i += 256) {
        int n = i / 12, c = (i % 12) * 4;
        uint32_t so = (uint32_t)(n * NSTR + c) * 4u;
        cp_async16(kzBase + so, gk + n * 48 + c);
        cp_async16(kzBase + TILE_B + so, gz + n * 48 + c);
    }
    CP_COMMIT();

    // stage Q (vectorized)
    {
        const uint4* gq4 = (const uint4*)gq;
        for (int i = tid; i < 1536; i += 256) {
            int n = i / 12, c4 = i % 12;
            *(uint4*)((char*)dsm + (uint32_t)(n * NSTR) * 4u + c4 * 16u) = gq4[n * 12 + c4];
        }
    }
    __syncthreads();

    const int l8 = lane & 7;
    const int khalf = ((lane >> 3) & 1) * 8;

    unsigned aQ[6][4];
#pragma unroll
    for (int kt = 0; kt < 6; kt++) {
        uint32_t ad = sQb + (uint32_t)((w * 16 + l8 + khalf) * (2 * NSTR) + kt * 16 + (lane >> 4) * 8) * 2u;
        LDSM4(aQ[kt], ad);
    }

    float o[12][4];
#pragma unroll
    for (int ft = 0; ft < 12; ft++)
#pragma unroll
        for (int c = 0; c < 4; c++) o[ft][c] = 0.f;
    float l0 = 0.f, l1 = 0.f;
    const float SCL2 = 0.1472441765f;

    // per-lane offsets (halves) for S-phase LDSM4 / PV-phase LDSM4T
    const uint32_t sOffK = (uint32_t)((((lane >> 4) & 1) * 8 + l8) * (2 * NSTR) + ((lane >> 3) & 1) * 8) * 2u;
    const uint32_t sOffZ = (uint32_t)((((lane >> 3) & 1) * 8 + l8) * (2 * NSTR) + ((lane >> 4) & 1) * 8) * 2u;

    for (int nt = 0; nt < 16; nt++) {
        CP_WAIT0();
        __syncthreads();
        if (nt < 15) {
            uint32_t kb = kzBase + ((nt + 1) & 1) * (2 * TILE_B);
            const unsigned* gks = gk + (size_t)(nt + 1) * 128 * 48;
            const unsigned* gzs = gz + (size_t)(nt + 1) * 128 * 48;
            for (int i = tid; i < 1536; i += 256) {
                int n = i / 12, c = (i % 12) * 4;
                uint32_t so = (uint32_t)(n * NSTR + c) * 4u;
                cp_async16(kb + so, gks + n * 48 + c);
                cp_async16(kb + TILE_B + so, gzs + n * 48 + c);
            }
            CP_COMMIT();
        }
        const uint32_t kCur = kzBase + (nt & 1) * (2 * TILE_B);
        const uint32_t zCur = kCur + TILE_B;

        unsigned P[8][4];
#pragma unroll
        for (int jj = 0; jj < 8; jj++) {
            float s0[4] = {0.f, 0.f, 0.f, 0.f}, s1[4] = {0.f, 0.f, 0.f, 0.f};
            uint32_t rowb = kCur + (uint32_t)(jj * 16 * 2 * NSTR) * 2u + sOffK;
#pragma unroll
            for (int kt = 0; kt < 6; kt++) {
                unsigned r[4];
                LDSM4(r, rowb + (uint32_t)(kt * 16) * 2u);
                MMA16816(s0, aQ[kt], r[0], r[1]);
                MMA16816(s1, aQ[kt], r[2], r[3]);
            }
            float e00 = fexp2(s0[0] * SCL2), e01 = fexp2(s0[1] * SCL2);
            float e02 = fexp2(s0[2] * SCL2), e03 = fexp2(s0[3] * SCL2);
            float e10 = fexp2(s1[0] * SCL2), e11 = fexp2(s1[1] * SCL2);
            float e12 = fexp2(s1[2] * SCL2), e13 = fexp2(s1[3] * SCL2);
            l0 += (e00 + e01) + (e10 + e11);
            l1 += (e02 + e03) + (e12 + e13);
            P[jj][0] = pack_h2(e00, e01);
            P[jj][1] = pack_h2(e02, e03);
            P[jj][2] = pack_h2(e10, e11);
            P[jj][3] = pack_h2(e12, e13);
        }

#pragma unroll
        for (int kk = 0; kk < 8; kk++) {
            uint32_t rowb = zCur + (uint32_t)(kk * 16 * 2 * NSTR) * 2u + sOffZ;
#pragma unroll
            for (int ftp = 0; ftp < 6; ftp++) {
                unsigned r[4];
                LDSM4T(r, rowb + (uint32_t)(ftp * 16) * 2u);
                MMA16816(o[2 * ftp],     P[kk], r[0], r[1]);
                MMA16816(o[2 * ftp + 1], P[kk], r[2], r[3]);
            }
        }
    }

    l0 += __shfl_xor_sync(0xffffffffu, l0, 1);
    l0 += __shfl_xor_sync(0xffffffffu, l0, 2);
    l1 += __shfl_xor_sync(0xffffffffu, l1, 1);
    l1 += __shfl_xor_sync(0xffffffffu, l1, 2);
    float inv0 = 1.f / l0, inv1 = 1.f / l1;

    int grow = m0 + w * 16 + (lane >> 2);
#pragma unroll
    for (int ft = 0; ft < 12; ft++) {
        int f0 = ft * 8 + (lane & 3) * 2, f1 = f0 + 1;
        int d0 = f0 % 3, c0 = f0 / 3, d1 = f1 % 3, c1 = f1 / 3;
        size_t a0 = ((size_t)(b * 3 + d0) * CDIM + h * 32 + c0) * SEQ + grow;
        size_t a1 = ((size_t)(b * 3 + d1) * CDIM + h * 32 + c1) * SEQ + grow;
        g_att2[a0]     = __float2half(o[ft][0] * inv0);
        g_att2[a1]     = __float2half(o[ft][1] * inv0);
        g_att2[a0 + 8] = __float2half(o[ft][2] * inv1);
        g_att2[a1 + 8] = __float2half(o[ft][3] * inv1);
    }
}

// ---------------------------------------------------------------------------
// Kernel 3: output VN-linear on HMMA, 512 threads + register prefetch.
// ---------------------------------------------------------------------------
__global__ __launch_bounds__(512, 1) void vn_out_kernel(
    const float* __restrict__ Wo, const float* __restrict__ bo, float* __restrict__ out)
{
    __shared__ __half sm2[16 * VNE + 16 * VNX];
    __half* sW = sm2;
    __half* sX = sm2 + 16 * VNE;

    const int tid = threadIdx.x;
    const int w = tid >> 5, lane = tid & 31;
    const int l8 = lane & 7, g = lane >> 2, t = lane & 3;
    const int b = blockIdx.z;
    const int ey = blockIdx.y, e0 = ey * 64;
    const int m0 = blockIdx.x * 128;

    const int we_ = (w & 3) * 16, wc_ = (w >> 2) * 96;
    const unsigned* att2w = (const unsigned*)g_att2;

    int wsi[2], wgi[2];
#pragma unroll
    for (int q = 0; q < 2; q++) {
        int i = q * 512 + tid, k = i >> 6, e = i & 63;
        wsi[q] = k * VNE + e;
        wgi[q] = k * CDIM + e0 + e;
    }
    int asi[6], agi[6];
#pragma unroll
    for (int q = 0; q < 6; q++) {
        int i = q * 512 + tid, k = i / 192, cw = i % 192;
        int d = cw / 64, mw = cw - d * 64;
        asi[q] = k * (VNX / 2) + d * 64 + mw;
        agi[q] = ((b * 3 + d) * CDIM + k) * (SEQ / 2) + (m0 >> 1) + mw;
    }

    float rW[2];
    unsigned rA[6];
#pragma unroll
    for (int q = 0; q < 2; q++) rW[q] = Wo[wgi[q]];
#pragma unroll
    for (int q = 0; q < 6; q++) rA[q] = att2w[agi[q]];

    float o[12][4];
#pragma unroll
    for (int p = 0; p < 12; p++)
#pragma unroll
        for (int c = 0; c < 4; c++) o[p][c] = 0.f;

    const uint32_t sWb = smem_u32(sW), sXb = smem_u32(sX);
    const int arow = ((lane >> 4) & 1) * 8 + l8, acol = ((lane >> 3) & 1) * 8;
    const uint32_t aAd = sWb + (uint32_t)(arow * VNE + we_ + acol) * 2u;
    const int brow = ((lane >> 3) & 1) * 8 + l8, bcol = ((lane >> 4) & 1) * 8;
    const uint32_t bAd0 = sXb + (uint32_t)(brow * VNX + wc_ + bcol) * 2u;
    unsigned* sXw = (unsigned*)sX;

    for (int kc = 0; kc < CDIM; kc += 16) {
#pragma unroll
        for (int q = 0; q < 2; q++) sW[wsi[q]] = __float2half(rW[q]);
#pragma unroll
        for (int q = 0; q < 6; q++) sXw[asi[q]] = rA[q];
        __syncthreads();
        if (kc + 16 < CDIM) {
#pragma unroll
            for (int q = 0; q < 2; q++) rW[q] = Wo[(kc + 16) * CDIM + wgi[q]];
#pragma unroll
            for (int q = 0; q < 6; q++) rA[q] = att2w[agi[q] + (kc + 16) * (SEQ / 2)];
        }
        unsigned aW[4];
        LDSM4T(aW, aAd);
#pragma unroll
        for (int p = 0; p < 6; p++) {
            unsigned r[4];
            LDSM4T(r, bAd0 + (uint32_t)(p * 32));
            MMA16816(o[2 * p],     aW, r[0], r[1]);
            MMA16816(o[2 * p + 1], aW, r[2], r[3]);
        }
        __syncthreads();
    }

    const int eg1 = we_ + g, eg2 = eg1 + 8;
    const int e1 = e0 + eg1, e2 = e0 + eg2;
    float u1[3], u2[3];
    {
        float a0 = bo[e1 * 3], a1 = bo[e1 * 3 + 1], a2 = bo[e1 * 3 + 2];
        float inv = EPSB * rsqrtf(a0 * a0 + a1 * a1 + a2 * a2);
        u1[0] = a0 * inv; u1[1] = a1 * inv; u1[2] = a2 * inv;
        float c0 = bo[e2 * 3], c1 = bo[e2 * 3 + 1], c2 = bo[e2 * 3 + 2];
        float inw = EPSB * rsqrtf(c0 * c0 + c1 * c1 + c2 * c2);
        u2[0] = c0 * inw; u2[1] = c1 * inw; u2[2] = c2 * inw;
    }

#pragma unroll
    for (int p = 0; p < 12; p++) {
        int col = wc_ + p * 8 + t * 2;
        int d = col >> 7, m = col & 127;
        size_t a1 = (((size_t)b * CDIM + e1) * 3 + d) * SEQ + m0 + m;
        size_t a2 = (((size_t)b * CDIM + e2) * 3 + d) * SEQ + m0 + m;
        out[a1]     = o[p][0] + u1[d];
        out[a1 + 1] = o[p][1] + u1[d];
        out[a2]     = o[p][2] + u2[d];
        out[a2 + 1] = o[p][3] + u2[d];
    }
}

// ---------------------------------------------------------------------------
extern "C" void kernel_launch(void* const* d_in, const int* in_sizes, int n_in,
                              void* d_out, int out_size)
{
    const float* Q   = (const float*)d_in[0];
    const float* K   = (const float*)d_in[1];
    const float* Z   = (const float*)d_in[2];
    const float* Wqw = (const float*)d_in[3];
    const float* Wqb = (const float*)d_in[4];
    const float* Wkw = (const float*)d_in[5];
    const float* Wkb = (const float*)d_in[6];
    const float* Wzw = (const float*)d_in[7];
    const float* Wzb = (const float*)d_in[8];
    const float* Wow = (const float*)d_in[9];
    const float* Wob = (const float*)d_in[10];
    float* out = (float*)d_out;

    cudaFuncSetAttribute(vn_in_kernel, cudaFuncAttributeMaxDynamicSharedMemorySize, VN_IN_SMEM);
    cudaFuncSetAttribute(attn_kernel, cudaFuncAttributeMaxDynamicSharedMemorySize, ATT_SMEM);

    vn_in_kernel<<<dim3(SEQ / 128, 4, 12), 512, VN_IN_SMEM>>>(
        Q, K, Z, Wqw, Wqb, Wkw, Wkb, Wzw, Wzb);
    attn_kernel<<<dim3(SEQ / 128, HEADS, BATCH), 256, ATT_SMEM>>>();
    vn_out_kernel<<<dim3(SEQ / 128, 4, BATCH), 512>>>(Wow, Wob, out);
}